// round 1
// baseline (speedup 1.0000x reference)
#include <cuda_runtime.h>
#include <cuda_bf16.h>
#include <math.h>

#define N_SAMPLES 65536
#define KNEG 10
#define DIM 128
#define WARPS_PER_BLOCK 8
#define THREADS (WARPS_PER_BLOCK * 32)
#define NBLOCKS (N_SAMPLES / WARPS_PER_BLOCK)   // 8192

__device__ float g_partial[NBLOCKS];

// numerically stable log-sigmoid: min(x,0) - log1p(exp(-|x|))
__device__ __forceinline__ float log_sigmoid(float x) {
    return fminf(x, 0.0f) - log1pf(expf(-fabsf(x)));
}

__device__ __forceinline__ float warp_sum(float v) {
    v += __shfl_xor_sync(0xFFFFFFFFu, v, 16);
    v += __shfl_xor_sync(0xFFFFFFFFu, v, 8);
    v += __shfl_xor_sync(0xFFFFFFFFu, v, 4);
    v += __shfl_xor_sync(0xFFFFFFFFu, v, 2);
    v += __shfl_xor_sync(0xFFFFFFFFu, v, 1);
    return v;
}

__global__ void __launch_bounds__(THREADS)
skipgram_loss_kernel(const int* __restrict__ input_idx,
                     const int* __restrict__ output_idx,
                     const int* __restrict__ neg_idx,
                     const float* __restrict__ W_in,
                     const float* __restrict__ W_out) {
    const int warp = threadIdx.x >> 5;
    const int lane = threadIdx.x & 31;
    const int n    = blockIdx.x * WARPS_PER_BLOCK + warp;

    // Gather the input vector: lane l holds floats [4l, 4l+4)
    const float4* in_row = reinterpret_cast<const float4*>(
        W_in + (size_t)input_idx[n] * DIM);
    const float4 a = in_row[lane];

    // Positive dot
    const float4* out_row = reinterpret_cast<const float4*>(
        W_out + (size_t)output_idx[n] * DIM);
    float4 b = out_row[lane];
    float dpos = a.x * b.x + a.y * b.y + a.z * b.z + a.w * b.w;
    dpos = warp_sum(dpos);

    float loss = log_sigmoid(dpos);

    // Negatives: prefetch all 10 row pointers, then unrolled gather+dot
    const int* nrow = neg_idx + (size_t)n * KNEG;
    int nidx[KNEG];
#pragma unroll
    for (int k = 0; k < KNEG; k++) nidx[k] = nrow[k];

    float dneg[KNEG];
#pragma unroll
    for (int k = 0; k < KNEG; k++) {
        const float4* r = reinterpret_cast<const float4*>(
            W_out + (size_t)nidx[k] * DIM);
        float4 c = r[lane];
        dneg[k] = a.x * c.x + a.y * c.y + a.z * c.z + a.w * c.w;
    }
#pragma unroll
    for (int k = 0; k < KNEG; k++) {
        float d = warp_sum(dneg[k]);
        loss += log_sigmoid(-d);
    }

    // Block reduce: lane 0 of each warp -> shared, warp 0 combines
    __shared__ float s[WARPS_PER_BLOCK];
    if (lane == 0) s[warp] = loss;
    __syncthreads();
    if (warp == 0) {
        float v = (lane < WARPS_PER_BLOCK) ? s[lane] : 0.0f;
        v += __shfl_xor_sync(0xFFFFFFFFu, v, 4);
        v += __shfl_xor_sync(0xFFFFFFFFu, v, 2);
        v += __shfl_xor_sync(0xFFFFFFFFu, v, 1);
        if (lane == 0) g_partial[blockIdx.x] = v;
    }
}

__global__ void __launch_bounds__(1024)
skipgram_reduce_kernel(float* __restrict__ out) {
    __shared__ float s[32];
    const int tid  = threadIdx.x;
    const int lane = tid & 31;
    const int warp = tid >> 5;

    float acc = 0.0f;
    for (int i = tid; i < NBLOCKS; i += 1024)
        acc += g_partial[i];
    acc = warp_sum(acc);
    if (lane == 0) s[warp] = acc;
    __syncthreads();
    if (warp == 0) {
        float v = s[lane];
        v = warp_sum(v);
        if (lane == 0) out[0] = v / (float)N_SAMPLES;
    }
}

extern "C" void kernel_launch(void* const* d_in, const int* in_sizes, int n_in,
                              void* d_out, int out_size) {
    const int*   input_idx  = (const int*)d_in[0];
    const int*   output_idx = (const int*)d_in[1];
    const int*   neg_idx    = (const int*)d_in[2];
    const float* W_in       = (const float*)d_in[3];
    const float* W_out      = (const float*)d_in[4];
    float*       out        = (float*)d_out;

    skipgram_loss_kernel<<<NBLOCKS, THREADS>>>(input_idx, output_idx, neg_idx,
                                               W_in, W_out);
    skipgram_reduce_kernel<<<1, 1024>>>(out);
}

// round 2
// speedup vs baseline: 1.0853x; 1.0853x over previous
#include <cuda_runtime.h>
#include <cuda_bf16.h>
#include <math.h>

#define N_SAMPLES 65536
#define KNEG 10
#define DIM 128
#define WARPS_PER_BLOCK 8
#define THREADS (WARPS_PER_BLOCK * 32)
#define NBLOCKS (N_SAMPLES / WARPS_PER_BLOCK)   // 8192

__device__ float        g_acc;      // zero at module load; self-resets each run
__device__ unsigned int g_count;    // arrival counter; self-resets each run

// numerically stable log-sigmoid: min(x,0) - log1p(exp(-|x|))
__device__ __forceinline__ float log_sigmoid(float x) {
    return fminf(x, 0.0f) - log1pf(expf(-fabsf(x)));
}

__device__ __forceinline__ float warp_sum(float v) {
    v += __shfl_xor_sync(0xFFFFFFFFu, v, 16);
    v += __shfl_xor_sync(0xFFFFFFFFu, v, 8);
    v += __shfl_xor_sync(0xFFFFFFFFu, v, 4);
    v += __shfl_xor_sync(0xFFFFFFFFu, v, 2);
    v += __shfl_xor_sync(0xFFFFFFFFu, v, 1);
    return v;
}

__global__ void __launch_bounds__(THREADS)
skipgram_loss_kernel(const int* __restrict__ input_idx,
                     const int* __restrict__ output_idx,
                     const int* __restrict__ neg_idx,
                     const float* __restrict__ W_in,
                     const float* __restrict__ W_out,
                     float* __restrict__ out) {
    const int warp = threadIdx.x >> 5;
    const int lane = threadIdx.x & 31;
    const int n    = blockIdx.x * WARPS_PER_BLOCK + warp;

    // Gather the input vector: lane l holds floats [4l, 4l+4)
    const float4* in_row = reinterpret_cast<const float4*>(
        W_in + (size_t)input_idx[n] * DIM);
    const float4 a = in_row[lane];

    // Positive dot
    const float4* out_row = reinterpret_cast<const float4*>(
        W_out + (size_t)output_idx[n] * DIM);
    float4 b = out_row[lane];
    float dpos = a.x * b.x + a.y * b.y + a.z * b.z + a.w * b.w;
    dpos = warp_sum(dpos);

    float loss = log_sigmoid(dpos);

    // Negatives: prefetch all 10 row indices, then unrolled gather+dot
    const int* nrow = neg_idx + (size_t)n * KNEG;
    int nidx[KNEG];
#pragma unroll
    for (int k = 0; k < KNEG; k++) nidx[k] = nrow[k];

    float dneg[KNEG];
#pragma unroll
    for (int k = 0; k < KNEG; k++) {
        const float4* r = reinterpret_cast<const float4*>(
            W_out + (size_t)nidx[k] * DIM);
        float4 c = r[lane];
        dneg[k] = a.x * c.x + a.y * c.y + a.z * c.z + a.w * c.w;
    }
#pragma unroll
    for (int k = 0; k < KNEG; k++) {
        float d = warp_sum(dneg[k]);
        loss += log_sigmoid(-d);
    }

    // Block reduce: lane 0 of each warp -> shared, warp 0 combines
    __shared__ float s[WARPS_PER_BLOCK];
    if (lane == 0) s[warp] = loss;
    __syncthreads();
    if (warp == 0 && lane == 0) {
        float v = 0.0f;
#pragma unroll
        for (int w = 0; w < WARPS_PER_BLOCK; w++) v += s[w];

        // Global accumulate + last-block finalize (replay-safe: exch resets)
        atomicAdd(&g_acc, v);
        __threadfence();
        unsigned int arrived = atomicAdd(&g_count, 1u);
        if (arrived == NBLOCKS - 1) {
            __threadfence();
            float total = atomicExch(&g_acc, 0.0f);   // read + reset
            out[0] = total * (1.0f / (float)N_SAMPLES);
            g_count = 0u;                              // reset for next replay
            __threadfence();
        }
    }
}

extern "C" void kernel_launch(void* const* d_in, const int* in_sizes, int n_in,
                              void* d_out, int out_size) {
    const int*   input_idx  = (const int*)d_in[0];
    const int*   output_idx = (const int*)d_in[1];
    const int*   neg_idx    = (const int*)d_in[2];
    const float* W_in       = (const float*)d_in[3];
    const float* W_out      = (const float*)d_in[4];
    float*       out        = (float*)d_out;

    skipgram_loss_kernel<<<NBLOCKS, THREADS>>>(input_idx, output_idx, neg_idx,
                                               W_in, W_out, out);
}

// round 3
// speedup vs baseline: 1.4642x; 1.3490x over previous
#include <cuda_runtime.h>
#include <cuda_bf16.h>
#include <math.h>

#define N_SAMPLES 65536
#define KNEG 10
#define DIM 128
#define WARPS_PER_BLOCK 8
#define THREADS (WARPS_PER_BLOCK * 32)
#define SAMPLES_PER_WARP 4
#define SAMPLES_PER_BLOCK (WARPS_PER_BLOCK * SAMPLES_PER_WARP)   // 32
#define NBLOCKS (N_SAMPLES / SAMPLES_PER_BLOCK)                  // 2048

__device__ float        g_acc;      // zero at module load; self-resets each run
__device__ unsigned int g_count;    // arrival counter; self-resets each run

// fast log-sigmoid: min(x,0) - log(1 + exp(-|x|)), MUFU-based
__device__ __forceinline__ float log_sigmoid(float x) {
    float t = __expf(-fabsf(x));
    return fminf(x, 0.0f) - __logf(1.0f + t);
}

// reduce within an aligned 8-lane group (value replicated across the group)
__device__ __forceinline__ float group8_sum(float v) {
    v += __shfl_xor_sync(0xFFFFFFFFu, v, 1);
    v += __shfl_xor_sync(0xFFFFFFFFu, v, 2);
    v += __shfl_xor_sync(0xFFFFFFFFu, v, 4);
    return v;
}

__device__ __forceinline__ float warp_sum(float v) {
    v += __shfl_xor_sync(0xFFFFFFFFu, v, 16);
    v += __shfl_xor_sync(0xFFFFFFFFu, v, 8);
    v += __shfl_xor_sync(0xFFFFFFFFu, v, 4);
    v += __shfl_xor_sync(0xFFFFFFFFu, v, 2);
    v += __shfl_xor_sync(0xFFFFFFFFu, v, 1);
    return v;
}

__global__ void __launch_bounds__(THREADS)
skipgram_loss_kernel(const int* __restrict__ input_idx,
                     const int* __restrict__ output_idx,
                     const int* __restrict__ neg_idx,
                     const float* __restrict__ W_in,
                     const float* __restrict__ W_out,
                     float* __restrict__ out) {
    const int warp = threadIdx.x >> 5;
    const int lane = threadIdx.x & 31;
    const int grp  = lane >> 3;          // 0..3: sample slot within warp
    const int gl   = lane & 7;           // lane within 8-lane group

    const int n = (blockIdx.x * WARPS_PER_BLOCK + warp) * SAMPLES_PER_WARP + grp;

    // Input vector: group's 8 lanes each hold 4 float4 (gl + 8j), fully coalesced
    const float4* in_row = reinterpret_cast<const float4*>(
        W_in + (size_t)input_idx[n] * DIM);
    float4 a0 = in_row[gl + 0];
    float4 a1 = in_row[gl + 8];
    float4 a2 = in_row[gl + 16];
    float4 a3 = in_row[gl + 24];

    // Positive dot
    const float4* out_row = reinterpret_cast<const float4*>(
        W_out + (size_t)output_idx[n] * DIM);
    float dpos;
    {
        float4 c0 = out_row[gl + 0];
        float4 c1 = out_row[gl + 8];
        float4 c2 = out_row[gl + 16];
        float4 c3 = out_row[gl + 24];
        dpos = a0.x*c0.x + a0.y*c0.y + a0.z*c0.z + a0.w*c0.w
             + a1.x*c1.x + a1.y*c1.y + a1.z*c1.z + a1.w*c1.w
             + a2.x*c2.x + a2.y*c2.y + a2.z*c2.z + a2.w*c2.w
             + a3.x*c3.x + a3.y*c3.y + a3.z*c3.z + a3.w*c3.w;
    }
    dpos = group8_sum(dpos);
    float loss = log_sigmoid(dpos);

    // Negatives
    const int* nrow = neg_idx + (size_t)n * KNEG;
    int nidx[KNEG];
#pragma unroll
    for (int k = 0; k < KNEG; k++) nidx[k] = nrow[k];

    float dneg[KNEG];
#pragma unroll
    for (int k = 0; k < KNEG; k++) {
        const float4* r = reinterpret_cast<const float4*>(
            W_out + (size_t)nidx[k] * DIM);
        float4 c0 = r[gl + 0];
        float4 c1 = r[gl + 8];
        float4 c2 = r[gl + 16];
        float4 c3 = r[gl + 24];
        dneg[k] = a0.x*c0.x + a0.y*c0.y + a0.z*c0.z + a0.w*c0.w
                + a1.x*c1.x + a1.y*c1.y + a1.z*c1.z + a1.w*c1.w
                + a2.x*c2.x + a2.y*c2.y + a2.z*c2.z + a2.w*c2.w
                + a3.x*c3.x + a3.y*c3.y + a3.z*c3.z + a3.w*c3.w;
    }
#pragma unroll
    for (int k = 0; k < KNEG; k++) {
        float d = group8_sum(dneg[k]);
        loss += log_sigmoid(-d);
    }

    // Per-block reduce: one leader per 8-lane group contributes
    __shared__ float s[SAMPLES_PER_BLOCK];
    if (gl == 0) s[warp * SAMPLES_PER_WARP + grp] = loss;
    __syncthreads();
    if (warp == 0) {
        float v = s[lane];          // SAMPLES_PER_BLOCK == 32 exactly
        v = warp_sum(v);
        if (lane == 0) {
            atomicAdd(&g_acc, v);
            __threadfence();
            unsigned int arrived = atomicAdd(&g_count, 1u);
            if (arrived == NBLOCKS - 1) {
                __threadfence();
                float total = atomicExch(&g_acc, 0.0f);   // read + reset
                out[0] = total * (1.0f / (float)N_SAMPLES);
                g_count = 0u;                              // reset for replay
                __threadfence();
            }
        }
    }
}

extern "C" void kernel_launch(void* const* d_in, const int* in_sizes, int n_in,
                              void* d_out, int out_size) {
    const int*   input_idx  = (const int*)d_in[0];
    const int*   output_idx = (const int*)d_in[1];
    const int*   neg_idx    = (const int*)d_in[2];
    const float* W_in       = (const float*)d_in[3];
    const float* W_out      = (const float*)d_in[4];
    float*       out        = (float*)d_out;

    skipgram_loss_kernel<<<NBLOCKS, THREADS>>>(input_idx, output_idx, neg_idx,
                                               W_in, W_out, out);
}